// round 1
// baseline (speedup 1.0000x reference)
#include <cuda_runtime.h>

#define NSAMP  2048   // 32 * 64
#define IMG_H  512
#define IMG_W  512
#define NCHAN  3
#define NTERMS (NSAMP * NCHAN)   // 6144

// reflect (numpy 'reflect', edge not repeated): -1 -> 1, H -> H-2
__device__ __forceinline__ int reflect_idx(int t) {
    t = (t < 0) ? -t : t;
    t = (t >= IMG_H) ? (2 * IMG_H - 2 - t) : t;   // H == W == 512
    return t;
}

__global__ void zero_out_kernel(float* out) {
    if (threadIdx.x == 0) out[0] = 0.0f;
}

__global__ __launch_bounds__(128)
void color_loss_kernel(const float* __restrict__ pred,   // [32,64,8]
                       const float* __restrict__ img,    // [32,3,512,512]
                       float* __restrict__ out)
{
    // 7-tap Gaussian, sigma=1, normalized (double-precision derived constants)
    const float kk[7] = {
        0.0044330481752437470f, 0.0540055826225118500f, 0.2420362293759061000f,
        0.3990502796524549000f,
        0.2420362293759061000f, 0.0540055826225118500f, 0.0044330481752437470f
    };

    const int t = blockIdx.x * blockDim.x + threadIdx.x;
    float local = 0.0f;

    if (t < NTERMS) {
        const int s = t / NCHAN;          // sample index 0..2047
        const int c = t - s * NCHAN;      // channel 0..2
        const int b = s >> 6;             // batch = s / 64

        const float* p = pred + (size_t)s * 8;
        const float px  = p[0];
        const float py  = p[1];
        const float col = p[5 + c];

        // matches: gx=2px-1; x=clip(((gx+1)*W-1)*0.5, 0, W-1)
        const float gx = 2.0f * px - 1.0f;
        const float gy = 2.0f * py - 1.0f;
        float x = ((gx + 1.0f) * (float)IMG_W - 1.0f) * 0.5f;
        float y = ((gy + 1.0f) * (float)IMG_H - 1.0f) * 0.5f;
        x = fminf(fmaxf(x, 0.0f), (float)(IMG_W - 1));
        y = fminf(fmaxf(y, 0.0f), (float)(IMG_H - 1));

        const float x0f = floorf(x);
        const float y0f = floorf(y);
        const float wx = x - x0f;
        const float wy = y - y0f;
        const int x0 = (int)x0f;
        const int y0 = (int)y0f;
        const bool xs = (x0 + 1 <= IMG_W - 1);  // x1 == x0+1 ? else clamped to x0
        const bool ys = (y0 + 1 <= IMG_H - 1);

        const float* base = img + ((size_t)b * NCHAN + c) * (size_t)(IMG_H * IMG_W);

        // union footprint: rows y0-3..y0+4, cols x0-3..x0+4  (8x8)
        int cx[8], ry[8];
        #pragma unroll
        for (int j = 0; j < 8; j++) cx[j] = reflect_idx(x0 - 3 + j);
        #pragma unroll
        for (int i = 0; i < 8; i++) ry[i] = reflect_idx(y0 - 3 + i);

        // load the whole window first (max MLP)
        float pv[8][8];
        #pragma unroll
        for (int i = 0; i < 8; i++) {
            const float* row = base + (size_t)ry[i] * IMG_W;
            #pragma unroll
            for (int j = 0; j < 8; j++) pv[i][j] = __ldg(&row[cx[j]]);
        }

        // horizontal blur: h0 = window at x0, hsh = window shifted by +1 (static)
        float h0[8], h1[8];
        #pragma unroll
        for (int i = 0; i < 8; i++) {
            float a0 = 0.0f, ash = 0.0f;
            #pragma unroll
            for (int j = 0; j < 7; j++) {
                a0  += kk[j] * pv[i][j];
                ash += kk[j] * pv[i][j + 1];
            }
            h0[i] = a0;
            h1[i] = xs ? ash : a0;      // x1 window (clamped case == x0 window)
        }

        // vertical blur: static 0-shift and +1-shift, select by ys
        float v00 = 0.0f, v01 = 0.0f, v00s = 0.0f, v01s = 0.0f;
        #pragma unroll
        for (int i = 0; i < 7; i++) {
            v00  += kk[i] * h0[i];
            v01  += kk[i] * h1[i];
            v00s += kk[i] * h0[i + 1];
            v01s += kk[i] * h1[i + 1];
        }
        const float v10 = ys ? v00s : v00;
        const float v11 = ys ? v01s : v01;

        const float target = v00 * (1.0f - wx) * (1.0f - wy)
                           + v01 * wx          * (1.0f - wy)
                           + v10 * (1.0f - wx) * wy
                           + v11 * wx          * wy;

        const float d = col - target;
        local = d * d * (1.0f / (float)NTERMS);
    }

    // intra-warp reduce
    #pragma unroll
    for (int o = 16; o > 0; o >>= 1)
        local += __shfl_down_sync(0xffffffffu, local, o);

    __shared__ float ws[4];
    const int lane = threadIdx.x & 31;
    const int wid  = threadIdx.x >> 5;
    if (lane == 0) ws[wid] = local;
    __syncthreads();
    if (wid == 0) {
        local = (lane < 4) ? ws[lane] : 0.0f;
        #pragma unroll
        for (int o = 2; o > 0; o >>= 1)
            local += __shfl_down_sync(0xffffffffu, local, o);
        if (lane == 0) atomicAdd(out, local);
    }
}

extern "C" void kernel_launch(void* const* d_in, const int* in_sizes, int n_in,
                              void* d_out, int out_size) {
    const float* pred = (const float*)d_in[0];
    const float* img  = (const float*)d_in[1];
    // defensive: identify predictions by its element count (32*64*8 = 16384)
    if (n_in >= 2 && in_sizes[0] != 32 * 64 * 8) {
        pred = (const float*)d_in[1];
        img  = (const float*)d_in[0];
    }
    float* out = (float*)d_out;

    zero_out_kernel<<<1, 32>>>(out);

    const int threads = 128;
    const int blocks  = (NTERMS + threads - 1) / threads;   // 48
    color_loss_kernel<<<blocks, threads>>>(pred, img, out);
}